// round 1
// baseline (speedup 1.0000x reference)
#include <cuda_runtime.h>
#include <cuda_bf16.h>
#include <math.h>
#include <stdint.h>

// Problem constants
#define BB 512
#define KK 256
#define NN 512
#define CC 6

#define LOG2E_F 1.4426950408889634f
#define LN2_F   0.6931471805599453f
#define LOG2PI_F 1.8378770664093453f  // log(2*pi)

// ---------------- scratch (static device globals; no allocation) -------------
// params per (b,k): {mu0, mu1, A, BA} {Cr, base2, 0, 0}
__device__ float4 g_params[BB * KK * 2];   // 4 MB
__device__ float  g_ce[BB * KK * CC];      // 3 MB
__device__ double g_spatial[BB];
__device__ double g_efs[BB];
__device__ double g_lambda[BB];
__device__ double g_gcnt[BB];

// ---------------- fast math helpers ------------------------------------------
__device__ __forceinline__ float ex2f(float x) {
    float y; asm("ex2.approx.ftz.f32 %0, %1;" : "=f"(y) : "f"(x)); return y;
}
__device__ __forceinline__ float lg2f(float x) {
    float y; asm("lg2.approx.ftz.f32 %0, %1;" : "=f"(y) : "f"(x)); return y;
}

__device__ __forceinline__ double warpRedD(double v) {
    #pragma unroll
    for (int o = 16; o; o >>= 1) v += __shfl_down_sync(0xffffffffu, v, o);
    return v;
}

// ---------------- kernel 1: per-(b,k) precompute ------------------------------
__global__ void prep_kernel(const float* __restrict__ pi,
                            const float* __restrict__ mu,
                            const float* __restrict__ L,
                            const float* __restrict__ ef_logits) {
    int i = blockIdx.x * blockDim.x + threadIdx.x;
    if (i >= BB * KK) return;

    float pv = pi[i];
    float a  = L[i * 4 + 0];
    float bb = L[i * 4 + 2];
    float c  = L[i * 4 + 3];

    // base (natural log): log(pi) - 0.5*(2*log(2pi) + 2*(log a + log c))
    // -> base2 in log2 domain
    float base_ln = logf(pv) - (LOG2PI_F + logf(a) + logf(c));
    float base2 = base_ln * LOG2E_F;

    float r = sqrtf(0.5f * LOG2E_F);   // folds -0.5*log2(e) into the quadratic

    float4 p0, p1;
    p0.x = mu[i * 2 + 0];
    p0.y = mu[i * 2 + 1];
    p0.z = r / a;        // A
    p0.w = bb / a;       // BA
    p1.x = r / c;        // Cr
    p1.y = base2;
    p1.z = 0.f; p1.w = 0.f;
    g_params[i * 2 + 0] = p0;
    g_params[i * 2 + 1] = p1;

    // CE table: lse(ef_logits[b,k,:]) - ef_logits[b,k,c]
    float e[CC];
    float mx = -INFINITY;
    #pragma unroll
    for (int c2 = 0; c2 < CC; c2++) { e[c2] = ef_logits[i * CC + c2]; mx = fmaxf(mx, e[c2]); }
    float s = 0.f;
    #pragma unroll
    for (int c2 = 0; c2 < CC; c2++) s += expf(e[c2] - mx);
    float lse = mx + logf(s);
    #pragma unroll
    for (int c2 = 0; c2 < CC; c2++) g_ce[i * CC + c2] = lse - e[c2];
}

// ---------------- kernel 2: main per-batch pass -------------------------------
__global__ __launch_bounds__(256) void main_kernel(const float* __restrict__ pi,
                                                   const float* __restrict__ tracks,
                                                   const uint32_t* __restrict__ mask) {
    const int b = blockIdx.x;
    const int tid = threadIdx.x;

    __shared__ float4 sp[KK * 2];        // 8 KB
    __shared__ float  sce[KK * CC];      // 6 KB
    __shared__ double red[8 * 4];

    // stage per-k params + CE into shared
    const float4* gp = g_params + (size_t)b * KK * 2;
    for (int i = tid; i < KK * 2; i += 256) sp[i] = gp[i];
    const float* gc = g_ce + (size_t)b * KK * CC;
    for (int i = tid; i < KK * CC; i += 256) sce[i] = gc[i];

    // Lambda contribution (K == 256 == blockDim)
    double lam = (double)pi[(size_t)b * KK + tid];

    __syncthreads();

    double spatial = 0.0, efs = 0.0, cnt = 0.0;

    for (int n = tid; n < NN; n += 256) {
        if (mask[(size_t)b * NN + n] == 0u) continue;
        const float* tr = tracks + ((size_t)b * NN + n) * 6;
        float x0 = tr[0], x1 = tr[1];
        int g = (int)tr[5];

        float m = -INFINITY, s = 0.f, t = 0.f;
        #pragma unroll 4
        for (int k = 0; k < KK; k++) {
            float4 a  = sp[2 * k];
            float4 c4 = sp[2 * k + 1];
            float d0 = x0 - a.x;
            float d1 = x1 - a.y;
            float v0 = d0 * a.z;
            float u  = fmaf(-a.w, d0, d1);
            float v1 = u * c4.x;
            float q  = fmaf(-v0, v0, fmaf(-v1, v1, c4.y));  // log2-domain logit
            float ce = sce[k * CC + g];

            float nm   = fmaxf(m, q);
            float corr = ex2f(m - nm);
            float p    = ex2f(q - nm);
            s = fmaf(s, corr, p);
            t = fmaf(t, corr, p * ce);
            m = nm;
        }
        float logmix = (m + lg2f(s)) * LN2_F;   // back to natural log
        spatial -= (double)logmix;
        efs     += (double)(t / s);
        cnt     += 1.0;
    }

    // block reduce 4 doubles
    spatial = warpRedD(spatial);
    efs     = warpRedD(efs);
    cnt     = warpRedD(cnt);
    lam     = warpRedD(lam);
    int wid = tid >> 5, lid = tid & 31;
    if (lid == 0) {
        red[wid]      = spatial;
        red[8 + wid]  = efs;
        red[16 + wid] = cnt;
        red[24 + wid] = lam;
    }
    __syncthreads();
    if (tid == 0) {
        double s0 = 0, s1 = 0, s2 = 0, s3 = 0;
        #pragma unroll
        for (int w = 0; w < 8; w++) { s0 += red[w]; s1 += red[8 + w]; s2 += red[16 + w]; s3 += red[24 + w]; }
        g_spatial[b] = s0;
        g_efs[b]     = s1;
        g_gcnt[b]    = s2;
        g_lambda[b]  = s3;
    }
}

// ---------------- kernel 3: finalize ------------------------------------------
__global__ void finalize_kernel(float* __restrict__ out) {
    const int tid = threadIdx.x;
    __shared__ double red[8 * 5];

    double lamSum = 0, cntSum = 0, l1Sum = 0, spSum = 0, efSum = 0;
    for (int b = tid; b < BB; b += 256) {
        double lam = g_lambda[b];
        double gc  = g_gcnt[b];
        lamSum += lam;
        cntSum += gc;
        l1Sum  += fabs(lam - gc) * sqrt(gc + 1.0);
        spSum  += g_spatial[b];
        efSum  += g_efs[b];
    }
    lamSum = warpRedD(lamSum);
    cntSum = warpRedD(cntSum);
    l1Sum  = warpRedD(l1Sum);
    spSum  = warpRedD(spSum);
    efSum  = warpRedD(efSum);
    int wid = tid >> 5, lid = tid & 31;
    if (lid == 0) {
        red[wid]      = lamSum;
        red[8 + wid]  = cntSum;
        red[16 + wid] = l1Sum;
        red[24 + wid] = spSum;
        red[32 + wid] = efSum;
    }
    __syncthreads();
    if (tid == 0) {
        double a0 = 0, a1 = 0, a2 = 0, a3 = 0, a4 = 0;
        #pragma unroll
        for (int w = 0; w < 8; w++) {
            a0 += red[w]; a1 += red[8 + w]; a2 += red[16 + w]; a3 += red[24 + w]; a4 += red[32 + w];
        }
        double count_loss = a0 / (double)BB;
        double n_total    = a1 > 1.0 ? a1 : 1.0;
        double count_l1   = a2 / (double)BB;
        double spatial    = a3 / n_total;
        double ef         = a4 / n_total;
        double total = count_loss + spatial + ef + count_l1;
        out[0] = (float)total;
        out[1] = (float)spatial;
        out[2] = (float)count_loss;
        out[3] = (float)count_l1;
        out[4] = (float)ef;
    }
}

// ---------------- launch -------------------------------------------------------
extern "C" void kernel_launch(void* const* d_in, const int* in_sizes, int n_in,
                              void* d_out, int out_size) {
    const float* pi        = (const float*)d_in[0];
    const float* mu        = (const float*)d_in[1];
    const float* L         = (const float*)d_in[2];
    const float* ef_logits = (const float*)d_in[3];
    const float* tracks    = (const float*)d_in[4];
    const uint32_t* mask   = (const uint32_t*)d_in[5];  // bool -> 4-byte 0/nonzero

    prep_kernel<<<(BB * KK + 255) / 256, 256>>>(pi, mu, L, ef_logits);
    main_kernel<<<BB, 256>>>(pi, tracks, mask);
    finalize_kernel<<<1, 256>>>((float*)d_out);
}

// round 2
// speedup vs baseline: 1.6987x; 1.6987x over previous
#include <cuda_runtime.h>
#include <cuda_bf16.h>
#include <math.h>
#include <stdint.h>

// Problem constants
#define BB 512
#define KK 256
#define NN 512
#define CC 6
#define HALF_N 256   // tracks per block (2 blocks per batch)

#define LOG2E_F 1.4426950408889634f
#define LN2_F   0.6931471805599453f
#define LOG2PI_LOG2E_F 2.651496129472319f  // log(2*pi) * log2(e) = log2(2*pi)
#define RQ_F 0.8493218002880191f           // sqrt(0.5 * log2(e))

// ---------------- scratch (static device globals; no allocation) -------------
__device__ double g_spatial[2 * BB];
__device__ double g_efs[2 * BB];
__device__ double g_lambda[2 * BB];
__device__ double g_gcnt[2 * BB];

// ---------------- fast math helpers ------------------------------------------
__device__ __forceinline__ float ex2f(float x) {
    float y; asm("ex2.approx.ftz.f32 %0, %1;" : "=f"(y) : "f"(x)); return y;
}
__device__ __forceinline__ float lg2f(float x) {
    float y; asm("lg2.approx.ftz.f32 %0, %1;" : "=f"(y) : "f"(x)); return y;
}

__device__ __forceinline__ double warpRedD(double v) {
    #pragma unroll
    for (int o = 16; o; o >>= 1) v += __shfl_down_sync(0xffffffffu, v, o);
    return v;
}

// ---------------- main kernel: fused prep + per-track pass --------------------
__global__ __launch_bounds__(256) void main_kernel(
    const float* __restrict__ pi,
    const float* __restrict__ mu,
    const float* __restrict__ L,
    const float* __restrict__ ef_logits,
    const float* __restrict__ tracks,
    const uint32_t* __restrict__ mask)
{
    const int bid  = blockIdx.x;
    const int b    = bid >> 1;
    const int half = bid & 1;
    const int tid  = threadIdx.x;

    __shared__ float4 sp[KK * 2];      // per-k: {mu0, mu1, A, BA} {Cr, base2, -, -}
    __shared__ float  sce[KK * CC];    // per-k CE table
    __shared__ double red[8 * 4];

    // Lambda contribution: only half 0 accumulates pi (K == blockDim == 256)
    double lam = (half == 0) ? (double)pi[(size_t)b * KK + tid] : 0.0;

    const int n0 = half * HALF_N;
    // prefix mask: if first track of this block's range is inactive, whole range is
    const bool blockActive = (mask[(size_t)b * NN + n0] != 0u);

    double spatial = 0.0, efs = 0.0, cnt = 0.0;

    if (blockActive) {
        // ---- staging: thread tid computes params for k = tid ----
        {
            const int i = b * KK + tid;
            float pv = pi[i];
            float a  = L[i * 4 + 0];
            float bb = L[i * 4 + 2];
            float c  = L[i * 4 + 3];

            // base2 = log2(pi) - log2(2pi) - log2(a) - log2(c)  (always < 0)
            float base2 = lg2f(pv) - LOG2PI_LOG2E_F - lg2f(a) - lg2f(c);

            float4 p0, p1;
            p0.x = mu[i * 2 + 0];
            p0.y = mu[i * 2 + 1];
            p0.z = RQ_F / a;     // A  (folds sqrt(0.5*log2e))
            p0.w = bb / a;       // BA
            p1.x = RQ_F / c;     // Cr
            p1.y = base2;
            p1.z = 0.f; p1.w = 0.f;
            sp[2 * tid]     = p0;
            sp[2 * tid + 1] = p1;

            // CE table: lse(ef_logits) - ef_logits[c]
            float e[CC];
            float mx = -INFINITY;
            #pragma unroll
            for (int c2 = 0; c2 < CC; c2++) {
                e[c2] = ef_logits[(size_t)i * CC + c2];
                mx = fmaxf(mx, e[c2]);
            }
            float ssum = 0.f;
            #pragma unroll
            for (int c2 = 0; c2 < CC; c2++) ssum += ex2f((e[c2] - mx) * LOG2E_F);
            float lse = mx + lg2f(ssum) * LN2_F;
            #pragma unroll
            for (int c2 = 0; c2 < CC; c2++) sce[tid * CC + c2] = lse - e[c2];
        }
        __syncthreads();

        // ---- per-track pass: thread tid owns track n0 + tid ----
        const int n = n0 + tid;
        if (mask[(size_t)b * NN + n] != 0u) {
            const float* tr = tracks + ((size_t)b * NN + n) * 6;
            float x0 = tr[0], x1 = tr[1];
            int g = (int)tr[5];
            const float* cep = sce + g;

            float s = 0.f, t = 0.f;
            #pragma unroll 4
            for (int k = 0; k < KK; k++) {
                float4 a4 = sp[2 * k];
                float4 c4 = sp[2 * k + 1];
                float d0 = x0 - a4.x;
                float d1 = x1 - a4.y;
                float v0 = d0 * a4.z;
                float u  = fmaf(-a4.w, d0, d1);
                float v1 = u * c4.x;
                float q  = fmaf(-v0, v0, fmaf(-v1, v1, c4.y));  // <= 0 always
                float p  = ex2f(q);                              // fixed shift M=0
                s += p;
                t = fmaf(p, cep[k * CC], t);
            }
            spatial = -(double)(lg2f(s) * LN2_F);
            efs     = (double)(t / s);
            cnt     = 1.0;
        }
    }

    // ---- block reduce 4 doubles (all threads reach here; uniform control) ----
    spatial = warpRedD(spatial);
    efs     = warpRedD(efs);
    cnt     = warpRedD(cnt);
    lam     = warpRedD(lam);
    const int wid = tid >> 5, lid = tid & 31;
    if (lid == 0) {
        red[wid]      = spatial;
        red[8 + wid]  = efs;
        red[16 + wid] = cnt;
        red[24 + wid] = lam;
    }
    __syncthreads();
    if (tid == 0) {
        double s0 = 0, s1 = 0, s2 = 0, s3 = 0;
        #pragma unroll
        for (int w = 0; w < 8; w++) {
            s0 += red[w]; s1 += red[8 + w]; s2 += red[16 + w]; s3 += red[24 + w];
        }
        g_spatial[bid] = s0;
        g_efs[bid]     = s1;
        g_gcnt[bid]    = s2;
        g_lambda[bid]  = s3;
    }
}

// ---------------- finalize ----------------------------------------------------
__global__ void finalize_kernel(float* __restrict__ out) {
    const int tid = threadIdx.x;
    __shared__ double red[8 * 5];

    double lamSum = 0, cntSum = 0, l1Sum = 0, spSum = 0, efSum = 0;
    for (int b = tid; b < BB; b += 256) {
        double lamb = g_lambda[2 * b] + g_lambda[2 * b + 1];
        double gc   = g_gcnt[2 * b]   + g_gcnt[2 * b + 1];
        lamSum += lamb;
        cntSum += gc;
        l1Sum  += fabs(lamb - gc) * sqrt(gc + 1.0);
        spSum  += g_spatial[2 * b] + g_spatial[2 * b + 1];
        efSum  += g_efs[2 * b]     + g_efs[2 * b + 1];
    }
    lamSum = warpRedD(lamSum);
    cntSum = warpRedD(cntSum);
    l1Sum  = warpRedD(l1Sum);
    spSum  = warpRedD(spSum);
    efSum  = warpRedD(efSum);
    const int wid = tid >> 5, lid = tid & 31;
    if (lid == 0) {
        red[wid]      = lamSum;
        red[8 + wid]  = cntSum;
        red[16 + wid] = l1Sum;
        red[24 + wid] = spSum;
        red[32 + wid] = efSum;
    }
    __syncthreads();
    if (tid == 0) {
        double a0 = 0, a1 = 0, a2 = 0, a3 = 0, a4 = 0;
        #pragma unroll
        for (int w = 0; w < 8; w++) {
            a0 += red[w]; a1 += red[8 + w]; a2 += red[16 + w];
            a3 += red[24 + w]; a4 += red[32 + w];
        }
        double count_loss = a0 / (double)BB;
        double n_total    = a1 > 1.0 ? a1 : 1.0;
        double count_l1   = a2 / (double)BB;
        double spatial    = a3 / n_total;
        double ef         = a4 / n_total;
        double total = count_loss + spatial + ef + count_l1;
        out[0] = (float)total;
        out[1] = (float)spatial;
        out[2] = (float)count_loss;
        out[3] = (float)count_l1;
        out[4] = (float)ef;
    }
}

// ---------------- launch -------------------------------------------------------
extern "C" void kernel_launch(void* const* d_in, const int* in_sizes, int n_in,
                              void* d_out, int out_size) {
    const float* pi        = (const float*)d_in[0];
    const float* mu        = (const float*)d_in[1];
    const float* L         = (const float*)d_in[2];
    const float* ef_logits = (const float*)d_in[3];
    const float* tracks    = (const float*)d_in[4];
    const uint32_t* mask   = (const uint32_t*)d_in[5];

    main_kernel<<<2 * BB, 256>>>(pi, mu, L, ef_logits, tracks, mask);
    finalize_kernel<<<1, 256>>>((float*)d_out);
}